// round 16
// baseline (speedup 1.0000x reference)
#include <cuda_runtime.h>
#include <cuda_fp16.h>
#include <math.h>
#include <cstdint>

#define B_ 64
#define C_ 273
#define T_ 2048
#define O_ 256
#define D_ 2048
#define NF 32
#define MTOT (B_*C_)      /* 17472 */
#define NPAD 17536        /* 137*128 */
#define QD (D_/2)         /* 1024 packed k-pair rows for stage 1 */
#define QC 144            /* 288/2 packed rows for stage 2 */

// ---------------- scratch (static device globals; no allocation) ----------------
__device__ __align__(16) __half2 g_EP[(size_t)QD * NPAD];  // E packed pairs [q][n] (~71.8MB)
__device__ __align__(16) __half2 g_hP[(size_t)QD * O_];    // heads packed [q][o] (1MB)
__device__ __align__(16) float   g_S [(size_t)O_ * MTOT];  // scores [o][b*273+c]
__device__ __align__(16) __half2 g_WP[(size_t)B_ * QC * O_]; // weights packed [b][q][o]

__device__ __forceinline__ uint32_t XM(int t){ return (uint32_t)((((t)&1)<<4) | (((t)&2)<<5)); }

__device__ __forceinline__ void cp_commit(){ asm volatile("cp.async.commit_group;\n"::); }
template<int N_> __device__ __forceinline__ void cp_wait(){ asm volatile("cp.async.wait_group %0;\n"::"n"(N_)); }
__device__ __forceinline__ void cpa16(void* dst, const void* src){
    unsigned d = (unsigned)__cvta_generic_to_shared(dst);
    asm volatile("cp.async.cg.shared.global [%0], [%1], 16;\n" :: "r"(d), "l"(src));
}
__device__ __forceinline__ void cpa16p(void* dst, const void* src, bool pred){
    unsigned d = (unsigned)__cvta_generic_to_shared(dst);
    int sz = pred ? 16 : 0;
    asm volatile("cp.async.cg.shared.global [%0], [%1], 16, %2;\n" :: "r"(d), "l"(src), "r"(sz));
}
// pack two f32 -> f16x2 (lo = first arg)
__device__ __forceinline__ uint32_t packh(float lo, float hi){
    uint32_t r; asm("cvt.rn.f16x2.f32 %0, %1, %2;" : "=r"(r) : "f"(hi), "f"(lo)); return r;
}

#define MMA16(acc, a0,a1,a2,a3, b0,b1) \
    asm volatile("mma.sync.aligned.m16n8k16.row.col.f32.f16.f16.f32 " \
        "{%0,%1,%2,%3}, {%4,%5,%6,%7}, {%8,%9}, {%0,%1,%2,%3};" \
        : "+f"(acc[0]), "+f"(acc[1]), "+f"(acc[2]), "+f"(acc[3]) \
        : "r"(a0), "r"(a1), "r"(a2), "r"(a3), "r"(b0), "r"(b1))

// ---------------- heads -> packed fp16 [q][o] ----------------
__global__ void hprep_kernel(const float* __restrict__ heads){
    __shared__ float2 t[32][33];
    int q0 = blockIdx.x*32, o0 = blockIdx.y*32;
    int tx = threadIdx.x, ty = threadIdx.y;   // 32 x 8
    #pragma unroll
    for (int i = 0; i < 4; i++){
        int o = o0 + ty + 8*i, q = q0 + tx;
        t[ty+8*i][tx] = *(const float2*)(heads + (size_t)o*D_ + 2*q);
    }
    __syncthreads();
    #pragma unroll
    for (int i = 0; i < 4; i++){
        int q = q0 + ty + 8*i, o = o0 + tx;
        float2 v = t[tx][ty+8*i];
        g_hP[(size_t)q*O_ + o] = __floats2half2_rn(v.x, v.y);
    }
}

// ---------------- E generator -> packed fp16 pairs [q][n] ----------------
__global__ void etgen_kernel(const float* __restrict__ positions){
    __shared__ float tc[2][NF][NF+1];
    __shared__ float ts[2][NF][NF+1];
    int n0 = blockIdx.x * 32;
    int tid = threadIdx.x;           // 256 threads
    const float twopi_w = 6.28318530717958647692f / 1.4f;
    #pragma unroll
    for (int u = 0; u < 8; u++){
        int idx   = tid + 256*u;
        int which = idx >> 10;
        int rem   = idx & 1023;
        int i     = rem >> 5;
        int r     = rem & 31;
        int n     = n0 + r;
        float c = 0.f, s = 0.f;
        if (n < MTOT){
            float p = positions[2*n + which] + 0.2f;
            sincosf((float)i * (p * twopi_w), &s, &c);
        }
        tc[which][i][r] = c;
        ts[which][i][r] = s;
    }
    __syncthreads();
    int r  = tid & 31;
    int qb = tid >> 5;
    #pragma unroll 4
    for (int q = qb; q < QD; q += 8){
        int d = 2*q;
        int m = d & 1023;
        int i = m >> 5, j = m & 31;     // j even, j+1 <= 31
        bool hi = (d >= 1024);
        float cx = tc[0][i][r],   sx = ts[0][i][r];
        float cy0 = tc[1][j][r],  sy0 = ts[1][j][r];
        float cy1 = tc[1][j+1][r],sy1 = ts[1][j+1][r];
        float v0 = hi ? (sx*cy0 + cx*sy0) : (cx*cy0 - sx*sy0);
        float v1 = hi ? (sx*cy1 + cx*sy1) : (cx*cy1 - sx*sy1);
        g_EP[(size_t)q * NPAD + n0 + r] = __floats2half2_rn(v0, v1);
    }
}

// =================================================================================
// GEMM1: S[m=o][n=bc] = sum_k heads[o][k] * E[n][k]   (M=256 full, N tiles of 128)
// 6-slot ring, issue lead 5, wait<3> (stages it and it+1 guaranteed). R15-exact.
// =================================================================================
#define G1_STG 24576            /* A 16KB + B 8KB */
#define G1_SLOTS 6
#define G1_SMEM (G1_SLOTS*G1_STG)   /* 147456 */
#define G1_NIT (D_/32)          /* 64 */

__global__ void __launch_bounds__(256,1) gemm1_h(
    const __half2* __restrict__ Ah, const __half2* __restrict__ Bh, float* __restrict__ S)
{
    extern __shared__ char sm[];
    int n0 = blockIdx.x*128;
    int tid = threadIdx.x, warp = tid>>5, lane = tid&31;
    int g = lane>>2, tg = lane&3;
    int wm = (warp>>1)*64, wn = (warp&1)*64;
    const uint32_t xm = XM(tg);

    float acc[4][8][4];
    #pragma unroll
    for (int mt = 0; mt < 4; mt++)
        #pragma unroll
        for (int nt = 0; nt < 8; nt++)
            #pragma unroll
            for (int e = 0; e < 4; e++) acc[mt][nt][e] = 0.f;

    auto load_stage = [&](int s, int it){
        char* dA = sm + s*G1_STG;
        char* dB = dA + 16384;
        int q0 = it*16;
        #pragma unroll
        for (int j = 0; j < 4; j++){       // A: 16 rows x 64 chunks
            int id = tid + 256*j;
            int r = id >> 6, ch = id & 63;
            uint32_t xr = XM(r&3);
            const char* src = (const char*)(Ah + (size_t)(q0+r)*O_) + 16*ch;
            cpa16(dA + r*1024 + (((uint32_t)(16*ch)) ^ xr), src);
        }
        #pragma unroll
        for (int j = 0; j < 2; j++){       // B: 16 rows x 32 chunks
            int id = tid + 256*j;
            int r = id >> 5, ch = id & 31;
            uint32_t xr = XM(r&3);
            const char* src = (const char*)(Bh + (size_t)(q0+r)*NPAD + n0) + 16*ch;
            cpa16(dB + r*512 + (((uint32_t)(16*ch)) ^ xr), src);
        }
        cp_commit();
    };

    uint32_t Af0[16], Bf0[16], Af1[16], Bf1[16];

    auto frag_load = [&](int slot, int h, uint32_t* Af, uint32_t* Bf){
        const char* dA = sm + slot*G1_STG;
        const char* dB = dA + 16384;
        int rA = tg + 8*h;
        uint32_t ab = (uint32_t)((wm + 8*g)*4);
        uint4 A0 = *(const uint4*)(dA + rA*1024     + ((ab   ) ^ xm));
        uint4 A1 = *(const uint4*)(dA + rA*1024     + ((ab+16) ^ xm));
        uint4 A2 = *(const uint4*)(dA + (rA+4)*1024 + ((ab   ) ^ xm));
        uint4 A3 = *(const uint4*)(dA + (rA+4)*1024 + ((ab+16) ^ xm));
        Af[0]=A0.x;  Af[1]=A0.y;  Af[2]=A0.z;  Af[3]=A0.w;
        Af[4]=A1.x;  Af[5]=A1.y;  Af[6]=A1.z;  Af[7]=A1.w;
        Af[8]=A2.x;  Af[9]=A2.y;  Af[10]=A2.z; Af[11]=A2.w;
        Af[12]=A3.x; Af[13]=A3.y; Af[14]=A3.z; Af[15]=A3.w;
        uint32_t bb = (uint32_t)((wn + 8*g)*4);
        uint4 B0 = *(const uint4*)(dB + rA*512      + ((bb   ) ^ xm));
        uint4 B1 = *(const uint4*)(dB + rA*512      + ((bb+16) ^ xm));
        uint4 B2 = *(const uint4*)(dB + (rA+4)*512  + ((bb   ) ^ xm));
        uint4 B3 = *(const uint4*)(dB + (rA+4)*512  + ((bb+16) ^ xm));
        Bf[0]=B0.x;  Bf[1]=B0.y;  Bf[2]=B0.z;  Bf[3]=B0.w;
        Bf[4]=B1.x;  Bf[5]=B1.y;  Bf[6]=B1.z;  Bf[7]=B1.w;
        Bf[8]=B2.x;  Bf[9]=B2.y;  Bf[10]=B2.z; Bf[11]=B2.w;
        Bf[12]=B3.x; Bf[13]=B3.y; Bf[14]=B3.z; Bf[15]=B3.w;
    };

    auto do_mma = [&](const uint32_t* Af, const uint32_t* Bf){
        #pragma unroll
        for (int mt = 0; mt < 4; mt++)
            #pragma unroll
            for (int nt = 0; nt < 8; nt++)
                MMA16(acc[mt][nt], Af[mt], Af[4+mt], Af[8+mt], Af[12+mt], Bf[nt], Bf[8+nt]);
    };

    load_stage(0,0); load_stage(1,1); load_stage(2,2); load_stage(3,3); load_stage(4,4);
    cp_wait<3>();
    __syncthreads();
    frag_load(0, 0, Af0, Bf0);

    #pragma unroll 1
    for (int it = 0; it < G1_NIT; it++){
        if (it > 0){ cp_wait<3>(); __syncthreads(); }
        if (it + 5 < G1_NIT) load_stage((it+5)%G1_SLOTS, it+5);
        else                 cp_commit();
        frag_load(it%G1_SLOTS, 1, Af1, Bf1);
        do_mma(Af0, Bf0);
        if (it + 1 < G1_NIT) frag_load((it+1)%G1_SLOTS, 0, Af0, Bf0);
        do_mma(Af1, Bf1);
    }

    int cb = n0 + wn + 16*tg;
    #pragma unroll
    for (int mt = 0; mt < 4; mt++){
        #pragma unroll
        for (int h = 0; h < 2; h++){
            int row = wm + 8*g + 4*h + mt;
            float* Cr = S + (size_t)row*MTOT;
            float4 v0, v1, v2, v3;
            v0.x=acc[mt][0][2*h];   v0.y=acc[mt][1][2*h];   v0.z=acc[mt][2][2*h];   v0.w=acc[mt][3][2*h];
            v1.x=acc[mt][4][2*h];   v1.y=acc[mt][5][2*h];   v1.z=acc[mt][6][2*h];   v1.w=acc[mt][7][2*h];
            v2.x=acc[mt][0][2*h+1]; v2.y=acc[mt][1][2*h+1]; v2.z=acc[mt][2][2*h+1]; v2.w=acc[mt][3][2*h+1];
            v3.x=acc[mt][4][2*h+1]; v3.y=acc[mt][5][2*h+1]; v3.z=acc[mt][6][2*h+1]; v3.w=acc[mt][7][2*h+1];
            if (cb      < MTOT) *(float4*)(Cr + cb     ) = v0;
            if (cb + 4  < MTOT) *(float4*)(Cr + cb + 4 ) = v1;
            if (cb + 8  < MTOT) *(float4*)(Cr + cb + 8 ) = v2;
            if (cb + 12 < MTOT) *(float4*)(Cr + cb + 12) = v3;
        }
    }
}

// =================================================================================
// GEMM2 (persistent v2): out[b][m=o][n=t] = sum_c W[b][o][c] * x[b][c][t]
// Grid = 128 CTAs, EXACTLY 8 items each (zero imbalance). n-tile fixed per CTA
// (n0 = (bid&15)*128); b walks (bid>>4) + 8w  -> 16 CTAs share each WP batch (L2).
// Continuous 5-slot ring across item boundaries; counters, no div/mod.
// Ring params = R15 (lead 4, wait<2>).
// =================================================================================
#define G2_STG 32768            /* A 16KB + B 16KB */
#define G2_SLOTS 5
#define G2_SMEM (G2_SLOTS*G2_STG)   /* 163840 */
#define G2_GRID 128
#define G2_IPC 8                 /* items per CTA */
#define G2_NITI 9                /* iterations per item */
#define G2_TOT (G2_IPC*G2_NITI)  /* 72 */

__global__ void __launch_bounds__(256,1) gemm2_h(
    const __half2* __restrict__ WP, const float* __restrict__ xg, float* __restrict__ out)
{
    extern __shared__ char sm[];
    int bid = blockIdx.x;
    int tid = threadIdx.x, warp = tid>>5, lane = tid&31;
    int g = lane>>2, tg = lane&3;
    int wm = (warp>>1)*64, wn = (warp&1)*64;
    const uint32_t xm = XM(tg);

    const int n0 = (bid & 15) << 7;     // fixed n-tile
    const int b0 = bid >> 4;            // batch stride 8: b(w) = b0 + 8w

    float acc[4][8][4];
    #pragma unroll
    for (int mt = 0; mt < 4; mt++)
        #pragma unroll
        for (int nt = 0; nt < 8; nt++)
            #pragma unroll
            for (int e = 0; e < 4; e++) acc[mt][nt][e] = 0.f;

    auto load_stage = [&](int s, int w, int it){
        int b = b0 + 8*w;
        const __half2* Ah = WP + (size_t)b*QC*O_;
        const float*   Bx = xg + (size_t)b*C_*T_ + n0;
        char* dA = sm + s*G2_STG;
        char* dB = dA + 16384;
        int q0 = it*16, k0 = it*32;
        #pragma unroll
        for (int j = 0; j < 4; j++){       // A: 16 rows x 64 chunks
            int id = tid + 256*j;
            int r = id >> 6, ch = id & 63;
            uint32_t xr = XM(r&3);
            const char* src = (const char*)(Ah + (size_t)(q0+r)*O_) + 16*ch;
            cpa16(dA + r*1024 + (((uint32_t)(16*ch)) ^ xr), src);
        }
        #pragma unroll
        for (int j = 0; j < 4; j++){       // B: 32 fp32 rows x 32 chunks
            int id = tid + 256*j;
            int r = id >> 5, ch = id & 31;
            uint32_t xr = XM((r>>1)&3);
            bool pr = (k0 + r) < C_;
            const char* src = (const char*)(Bx + (size_t)(k0+r)*T_) + 16*ch;
            cpa16p(dB + r*512 + (((uint32_t)(16*ch)) ^ xr), src, pr);
        }
        cp_commit();
    };

    uint32_t Af0[16], Bp0[16], Af1[16], Bp1[16];

    auto frag_load = [&](int slot, int h, uint32_t* Af, uint32_t* Bp){
        const char* dA = sm + slot*G2_STG;
        const char* dB = dA + 16384;
        int rA = tg + 8*h;
        uint32_t ab = (uint32_t)((wm + 8*g)*4);
        uint4 A0 = *(const uint4*)(dA + rA*1024     + ((ab   ) ^ xm));
        uint4 A1 = *(const uint4*)(dA + rA*1024     + ((ab+16) ^ xm));
        uint4 A2 = *(const uint4*)(dA + (rA+4)*1024 + ((ab   ) ^ xm));
        uint4 A3 = *(const uint4*)(dA + (rA+4)*1024 + ((ab+16) ^ xm));
        Af[0]=A0.x;  Af[1]=A0.y;  Af[2]=A0.z;  Af[3]=A0.w;
        Af[4]=A1.x;  Af[5]=A1.y;  Af[6]=A1.z;  Af[7]=A1.w;
        Af[8]=A2.x;  Af[9]=A2.y;  Af[10]=A2.z; Af[11]=A2.w;
        Af[12]=A3.x; Af[13]=A3.y; Af[14]=A3.z; Af[15]=A3.w;

        int rB = 16*h;
        uint32_t bb = (uint32_t)((wn + 8*g)*4);
        uint32_t c0 = (bb   ) ^ xm;
        uint32_t c1 = (bb+16) ^ xm;
        float4 e0 = *(const float4*)(dB + (rB+2*tg  )*512 + c0);
        float4 e1 = *(const float4*)(dB + (rB+2*tg  )*512 + c1);
        float4 o0 = *(const float4*)(dB + (rB+2*tg+1)*512 + c0);
        float4 o1 = *(const float4*)(dB + (rB+2*tg+1)*512 + c1);
        float4 E0 = *(const float4*)(dB + (rB+2*tg+8)*512 + c0);
        float4 E1 = *(const float4*)(dB + (rB+2*tg+8)*512 + c1);
        float4 O0 = *(const float4*)(dB + (rB+2*tg+9)*512 + c0);
        float4 O1 = *(const float4*)(dB + (rB+2*tg+9)*512 + c1);
        Bp[0]=packh(e0.x,o0.x); Bp[1]=packh(e0.y,o0.y); Bp[2]=packh(e0.z,o0.z); Bp[3]=packh(e0.w,o0.w);
        Bp[4]=packh(e1.x,o1.x); Bp[5]=packh(e1.y,o1.y); Bp[6]=packh(e1.z,o1.z); Bp[7]=packh(e1.w,o1.w);
        Bp[8]=packh(E0.x,O0.x); Bp[9]=packh(E0.y,O0.y); Bp[10]=packh(E0.z,O0.z); Bp[11]=packh(E0.w,O0.w);
        Bp[12]=packh(E1.x,O1.x);Bp[13]=packh(E1.y,O1.y);Bp[14]=packh(E1.z,O1.z); Bp[15]=packh(E1.w,O1.w);
    };

    auto do_mma = [&](const uint32_t* Af, const uint32_t* Bp){
        #pragma unroll
        for (int mt = 0; mt < 4; mt++)
            #pragma unroll
            for (int nt = 0; nt < 8; nt++)
                MMA16(acc[mt][nt], Af[mt], Af[4+mt], Af[8+mt], Af[12+mt], Bp[nt], Bp[8+nt]);
    };

    // prologue: stages 0..3 of item 0
    load_stage(0, 0,0); load_stage(1, 0,1); load_stage(2, 0,2); load_stage(3, 0,3);
    cp_wait<2>();
    __syncthreads();
    frag_load(0, 0, Af0, Bp0);

    int wL = 0, itL = 4;     // decode of lead stage index gi+4
    int wC = 0, itC = 0;     // decode of current gi

    #pragma unroll 1
    for (int gi = 0; gi < G2_TOT; gi++){
        if (gi > 0){ cp_wait<2>(); __syncthreads(); }   // stages <= gi+1 resident
        if (gi + 4 < G2_TOT){
            int s = gi + 4; while (s >= G2_SLOTS) s -= G2_SLOTS;   // (gi+4)%5 cheap
            load_stage(s, wL, itL);
        } else cp_commit();
        if (++itL == G2_NITI){ itL = 0; wL++; }

        int slotC = gi; while (slotC >= G2_SLOTS) slotC -= G2_SLOTS;
        frag_load(slotC, 1, Af1, Bp1);
        do_mma(Af0, Bp0);
        if (gi + 1 < G2_TOT){
            int sn = gi + 1; while (sn >= G2_SLOTS) sn -= G2_SLOTS;
            frag_load(sn, 0, Af0, Bp0);
        }
        do_mma(Af1, Bp1);

        if (itC == G2_NITI - 1){
            // item complete: store + reset acc (overlaps in-flight cp.asyncs)
            int b = b0 + 8*wC;
            float* Cb = out + (size_t)b*O_*T_;
            int cb = n0 + wn + 16*tg;
            #pragma unroll
            for (int mt = 0; mt < 4; mt++){
                #pragma unroll
                for (int h = 0; h < 2; h++){
                    int row = wm + 8*g + 4*h + mt;
                    float* Cr = Cb + (size_t)row*T_;
                    float4 v0, v1, v2, v3;
                    v0.x=acc[mt][0][2*h];   v0.y=acc[mt][1][2*h];   v0.z=acc[mt][2][2*h];   v0.w=acc[mt][3][2*h];
                    v1.x=acc[mt][4][2*h];   v1.y=acc[mt][5][2*h];   v1.z=acc[mt][6][2*h];   v1.w=acc[mt][7][2*h];
                    v2.x=acc[mt][0][2*h+1]; v2.y=acc[mt][1][2*h+1]; v2.z=acc[mt][2][2*h+1]; v2.w=acc[mt][3][2*h+1];
                    v3.x=acc[mt][4][2*h+1]; v3.y=acc[mt][5][2*h+1]; v3.z=acc[mt][6][2*h+1]; v3.w=acc[mt][7][2*h+1];
                    *(float4*)(Cr + cb     ) = v0;
                    *(float4*)(Cr + cb + 4 ) = v1;
                    *(float4*)(Cr + cb + 8 ) = v2;
                    *(float4*)(Cr + cb + 12) = v3;
                }
            }
            #pragma unroll
            for (int mt = 0; mt < 4; mt++)
                #pragma unroll
                for (int nt = 0; nt < 8; nt++)
                    #pragma unroll
                    for (int e = 0; e < 4; e++) acc[mt][nt][e] = 0.f;
        }
        if (++itC == G2_NITI){ itC = 0; wC++; }
    }
}

// ---------------- softmax over C, writing packed fp16 W^T directly ----------------
#define WPITCH 277
__global__ void __launch_bounds__(256) softmaxT_kernel(
    const float* __restrict__ S, const unsigned char* __restrict__ mask,
    __half2* __restrict__ WP)
{
    __shared__ float wsm[32*WPITCH];
    const float NEG_INF = __int_as_float(0xff800000);
    int o0 = blockIdx.x * 32;
    int b  = blockIdx.y;
    int tid = threadIdx.x, wid = tid >> 5, lane = tid & 31;
    const unsigned char* mrow = mask + (size_t)b * C_;

    #pragma unroll
    for (int p = 0; p < 4; p++){
        int o = 4*wid + p;
        const float* row = S + (size_t)(o0 + o) * MTOT + (size_t)b * C_;
        float v[9];
        float vmax = NEG_INF;
        #pragma unroll
        for (int it = 0; it < 9; it++){
            int c = lane + 32*it;
            float s = NEG_INF;
            if (c < C_) s = mrow[c] ? NEG_INF : row[c];
            v[it] = s;
            vmax = fmaxf(vmax, s);
        }
        #pragma unroll
        for (int off = 16; off; off >>= 1)
            vmax = fmaxf(vmax, __shfl_xor_sync(0xffffffffu, vmax, off));
        float e[9], sum = 0.f;
        #pragma unroll
        for (int it = 0; it < 9; it++){
            e[it] = __expf(v[it] - vmax);
            sum += e[it];
        }
        #pragma unroll
        for (int off = 16; off; off >>= 1)
            sum += __shfl_xor_sync(0xffffffffu, sum, off);
        float inv = 1.f / sum;
        #pragma unroll
        for (int it = 0; it < 9; it++){
            int c = lane + 32*it;
            if (c < C_) wsm[o*WPITCH + c] = e[it] * inv;
        }
    }
    __syncthreads();

    __half2* base = WP + (size_t)b * QC * O_ + o0;
    for (int q = wid; q < QC; q += 8){
        int c0 = 2*q, c1 = 2*q + 1;
        float w0 = (c0 < C_) ? wsm[lane*WPITCH + c0] : 0.f;
        float w1 = (c1 < C_) ? wsm[lane*WPITCH + c1] : 0.f;
        base[(size_t)q * O_ + lane] = __floats2half2_rn(w0, w1);
    }
}

// ---------------- launcher ----------------
extern "C" void kernel_launch(void* const* d_in, const int* in_sizes, int n_in,
                              void* d_out, int out_size)
{
    const float* x = nullptr;
    const float* positions = nullptr;
    const unsigned char* mask = nullptr;
    const float* heads = nullptr;
    for (int i = 0; i < n_in; i++){
        long long s = in_sizes[i];
        if      (s == (long long)B_*C_*T_) x         = (const float*)d_in[i];
        else if (s == (long long)B_*C_*2 ) positions = (const float*)d_in[i];
        else if (s == (long long)B_*C_   ) mask      = (const unsigned char*)d_in[i];
        else if (s == (long long)O_*D_   ) heads     = (const float*)d_in[i];
    }

    __half2 *pEP, *pHP, *pWP;
    float *pS;
    cudaGetSymbolAddress((void**)&pEP, g_EP);
    cudaGetSymbolAddress((void**)&pHP, g_hP);
    cudaGetSymbolAddress((void**)&pS,  g_S);
    cudaGetSymbolAddress((void**)&pWP, g_WP);

    cudaFuncSetAttribute(gemm1_h, cudaFuncAttributeMaxDynamicSharedMemorySize, G1_SMEM);
    cudaFuncSetAttribute(gemm2_h, cudaFuncAttributeMaxDynamicSharedMemorySize, G2_SMEM);

    // 1) heads -> packed fp16 [q][o]
    hprep_kernel<<<dim3(QD/32, O_/32), dim3(32,8)>>>(heads);

    // 2) E -> packed fp16 pairs [q][n] (pad cols zero)
    etgen_kernel<<<NPAD/32, 256>>>(positions);

    // 3) scores: M=256(full), N=17472, K=2048   — 137 CTAs, single wave
    gemm1_h<<<dim3(NPAD/128, 1, 1), 256, G1_SMEM>>>(pHP, pEP, pS);

    // 4) softmax -> packed W^T [b][q][o]
    softmaxT_kernel<<<dim3(O_/32, B_), 256>>>(pS, mask, pWP);

    // 5) out = W @ x, persistent: 128 CTAs x exactly 8 (b, n-tile) items
    gemm2_h<<<G2_GRID, 256, G2_SMEM>>>(pWP, x, (float*)d_out);
}

// round 17
// speedup vs baseline: 1.1195x; 1.1195x over previous
#include <cuda_runtime.h>
#include <cuda_fp16.h>
#include <math.h>
#include <cstdint>

#define B_ 64
#define C_ 273
#define T_ 2048
#define O_ 256
#define D_ 2048
#define NF 32
#define MTOT (B_*C_)      /* 17472 */
#define NPAD 17536        /* 137*128 */
#define QD (D_/2)         /* 1024 packed k-pair rows for stage 1 */
#define QC 144            /* 288/2 packed rows for stage 2 */

// ---------------- scratch (static device globals; no allocation) ----------------
__device__ __align__(16) __half2 g_EP[(size_t)QD * NPAD];  // E packed pairs [q][n] (~71.8MB)
__device__ __align__(16) __half2 g_hP[(size_t)QD * O_];    // heads packed [q][o] (1MB)
__device__ __align__(16) float   g_S [(size_t)O_ * MTOT];  // scores [o][b*273+c]
__device__ __align__(16) __half2 g_WP[(size_t)B_ * QC * O_]; // weights packed [b][q][o]

__device__ __forceinline__ uint32_t XM(int t){ return (uint32_t)((((t)&1)<<4) | (((t)&2)<<5)); }

__device__ __forceinline__ void cp_commit(){ asm volatile("cp.async.commit_group;\n"::); }
template<int N_> __device__ __forceinline__ void cp_wait(){ asm volatile("cp.async.wait_group %0;\n"::"n"(N_)); }
__device__ __forceinline__ void cpa16(void* dst, const void* src){
    unsigned d = (unsigned)__cvta_generic_to_shared(dst);
    asm volatile("cp.async.cg.shared.global [%0], [%1], 16;\n" :: "r"(d), "l"(src));
}
__device__ __forceinline__ void cpa16p(void* dst, const void* src, bool pred){
    unsigned d = (unsigned)__cvta_generic_to_shared(dst);
    int sz = pred ? 16 : 0;
    asm volatile("cp.async.cg.shared.global [%0], [%1], 16, %2;\n" :: "r"(d), "l"(src), "r"(sz));
}
// pack two f32 -> f16x2 (lo = first arg)
__device__ __forceinline__ uint32_t packh(float lo, float hi){
    uint32_t r; asm("cvt.rn.f16x2.f32 %0, %1, %2;" : "=r"(r) : "f"(hi), "f"(lo)); return r;
}

#define MMA16(acc, a0,a1,a2,a3, b0,b1) \
    asm volatile("mma.sync.aligned.m16n8k16.row.col.f32.f16.f16.f32 " \
        "{%0,%1,%2,%3}, {%4,%5,%6,%7}, {%8,%9}, {%0,%1,%2,%3};" \
        : "+f"(acc[0]), "+f"(acc[1]), "+f"(acc[2]), "+f"(acc[3]) \
        : "r"(a0), "r"(a1), "r"(a2), "r"(a3), "r"(b0), "r"(b1))

// ---------------- heads -> packed fp16 [q][o] ----------------
__global__ void hprep_kernel(const float* __restrict__ heads){
    __shared__ float2 t[32][33];
    int q0 = blockIdx.x*32, o0 = blockIdx.y*32;
    int tx = threadIdx.x, ty = threadIdx.y;   // 32 x 8
    #pragma unroll
    for (int i = 0; i < 4; i++){
        int o = o0 + ty + 8*i, q = q0 + tx;
        t[ty+8*i][tx] = *(const float2*)(heads + (size_t)o*D_ + 2*q);
    }
    __syncthreads();
    #pragma unroll
    for (int i = 0; i < 4; i++){
        int q = q0 + ty + 8*i, o = o0 + tx;
        float2 v = t[tx][ty+8*i];
        g_hP[(size_t)q*O_ + o] = __floats2half2_rn(v.x, v.y);
    }
}

// ---------------- E generator -> packed fp16 pairs [q][n] ----------------
__global__ void etgen_kernel(const float* __restrict__ positions){
    __shared__ float tc[2][NF][NF+1];
    __shared__ float ts[2][NF][NF+1];
    int n0 = blockIdx.x * 32;
    int tid = threadIdx.x;           // 256 threads
    const float twopi_w = 6.28318530717958647692f / 1.4f;
    #pragma unroll
    for (int u = 0; u < 8; u++){
        int idx   = tid + 256*u;
        int which = idx >> 10;
        int rem   = idx & 1023;
        int i     = rem >> 5;
        int r     = rem & 31;
        int n     = n0 + r;
        float c = 0.f, s = 0.f;
        if (n < MTOT){
            float p = positions[2*n + which] + 0.2f;
            sincosf((float)i * (p * twopi_w), &s, &c);
        }
        tc[which][i][r] = c;
        ts[which][i][r] = s;
    }
    __syncthreads();
    int r  = tid & 31;
    int qb = tid >> 5;
    #pragma unroll 4
    for (int q = qb; q < QD; q += 8){
        int d = 2*q;
        int m = d & 1023;
        int i = m >> 5, j = m & 31;     // j even, j+1 <= 31
        bool hi = (d >= 1024);
        float cx = tc[0][i][r],   sx = ts[0][i][r];
        float cy0 = tc[1][j][r],  sy0 = ts[1][j][r];
        float cy1 = tc[1][j+1][r],sy1 = ts[1][j+1][r];
        float v0 = hi ? (sx*cy0 + cx*sy0) : (cx*cy0 - sx*sy0);
        float v1 = hi ? (sx*cy1 + cx*sy1) : (cx*cy1 - sx*sy1);
        g_EP[(size_t)q * NPAD + n0 + r] = __floats2half2_rn(v0, v1);
    }
}

// =================================================================================
// GEMM1: S[m=o][n=bc] = sum_k heads[o][k] * E[n][k]   (M=256 full, N tiles of 128)
// R15 schedule; 8-slot ring, issue lead 7, wait<5> (stages it and it+1 guaranteed;
// up to 5 stages / 120KB outstanding after the wait).
// 256 thr, 8 warps (4m x 2n), warp tile 64x64, XOR-swizzled smem.
// =================================================================================
#define G1_STG 24576            /* A 16KB + B 8KB */
#define G1_SLOTS 8
#define G1_SMEM (G1_SLOTS*G1_STG)   /* 196608 */
#define G1_NIT (D_/32)          /* 64 */

__global__ void __launch_bounds__(256,1) gemm1_h(
    const __half2* __restrict__ Ah, const __half2* __restrict__ Bh, float* __restrict__ S)
{
    extern __shared__ char sm[];
    int n0 = blockIdx.x*128;
    int tid = threadIdx.x, warp = tid>>5, lane = tid&31;
    int g = lane>>2, tg = lane&3;
    int wm = (warp>>1)*64, wn = (warp&1)*64;
    const uint32_t xm = XM(tg);

    float acc[4][8][4];
    #pragma unroll
    for (int mt = 0; mt < 4; mt++)
        #pragma unroll
        for (int nt = 0; nt < 8; nt++)
            #pragma unroll
            for (int e = 0; e < 4; e++) acc[mt][nt][e] = 0.f;

    auto load_stage = [&](int s, int it){
        char* dA = sm + s*G1_STG;
        char* dB = dA + 16384;
        int q0 = it*16;
        #pragma unroll
        for (int j = 0; j < 4; j++){       // A: 16 rows x 64 chunks
            int id = tid + 256*j;
            int r = id >> 6, ch = id & 63;
            uint32_t xr = XM(r&3);
            const char* src = (const char*)(Ah + (size_t)(q0+r)*O_) + 16*ch;
            cpa16(dA + r*1024 + (((uint32_t)(16*ch)) ^ xr), src);
        }
        #pragma unroll
        for (int j = 0; j < 2; j++){       // B: 16 rows x 32 chunks
            int id = tid + 256*j;
            int r = id >> 5, ch = id & 31;
            uint32_t xr = XM(r&3);
            const char* src = (const char*)(Bh + (size_t)(q0+r)*NPAD + n0) + 16*ch;
            cpa16(dB + r*512 + (((uint32_t)(16*ch)) ^ xr), src);
        }
        cp_commit();
    };

    uint32_t Af0[16], Bf0[16], Af1[16], Bf1[16];

    auto frag_load = [&](int slot, int h, uint32_t* Af, uint32_t* Bf){
        const char* dA = sm + slot*G1_STG;
        const char* dB = dA + 16384;
        int rA = tg + 8*h;
        uint32_t ab = (uint32_t)((wm + 8*g)*4);
        uint4 A0 = *(const uint4*)(dA + rA*1024     + ((ab   ) ^ xm));
        uint4 A1 = *(const uint4*)(dA + rA*1024     + ((ab+16) ^ xm));
        uint4 A2 = *(const uint4*)(dA + (rA+4)*1024 + ((ab   ) ^ xm));
        uint4 A3 = *(const uint4*)(dA + (rA+4)*1024 + ((ab+16) ^ xm));
        Af[0]=A0.x;  Af[1]=A0.y;  Af[2]=A0.z;  Af[3]=A0.w;
        Af[4]=A1.x;  Af[5]=A1.y;  Af[6]=A1.z;  Af[7]=A1.w;
        Af[8]=A2.x;  Af[9]=A2.y;  Af[10]=A2.z; Af[11]=A2.w;
        Af[12]=A3.x; Af[13]=A3.y; Af[14]=A3.z; Af[15]=A3.w;
        uint32_t bb = (uint32_t)((wn + 8*g)*4);
        uint4 B0 = *(const uint4*)(dB + rA*512      + ((bb   ) ^ xm));
        uint4 B1 = *(const uint4*)(dB + rA*512      + ((bb+16) ^ xm));
        uint4 B2 = *(const uint4*)(dB + (rA+4)*512  + ((bb   ) ^ xm));
        uint4 B3 = *(const uint4*)(dB + (rA+4)*512  + ((bb+16) ^ xm));
        Bf[0]=B0.x;  Bf[1]=B0.y;  Bf[2]=B0.z;  Bf[3]=B0.w;
        Bf[4]=B1.x;  Bf[5]=B1.y;  Bf[6]=B1.z;  Bf[7]=B1.w;
        Bf[8]=B2.x;  Bf[9]=B2.y;  Bf[10]=B2.z; Bf[11]=B2.w;
        Bf[12]=B3.x; Bf[13]=B3.y; Bf[14]=B3.z; Bf[15]=B3.w;
    };

    auto do_mma = [&](const uint32_t* Af, const uint32_t* Bf){
        #pragma unroll
        for (int mt = 0; mt < 4; mt++)
            #pragma unroll
            for (int nt = 0; nt < 8; nt++)
                MMA16(acc[mt][nt], Af[mt], Af[4+mt], Af[8+mt], Af[12+mt], Bf[nt], Bf[8+nt]);
    };

    // prologue: 7 stages committed; wait<5> -> stages 0,1 resident
    load_stage(0,0); load_stage(1,1); load_stage(2,2); load_stage(3,3);
    load_stage(4,4); load_stage(5,5); load_stage(6,6);
    cp_wait<5>();
    __syncthreads();
    frag_load(0, 0, Af0, Bf0);

    #pragma unroll 1
    for (int it = 0; it < G1_NIT; it++){
        if (it > 0){ cp_wait<5>(); __syncthreads(); }   // stages <= it+1 resident
        if (it + 7 < G1_NIT) load_stage((it+7)%G1_SLOTS, it+7);   // slot == (it-1)%8
        else                 cp_commit();
        frag_load(it%G1_SLOTS, 1, Af1, Bf1);
        do_mma(Af0, Bf0);
        if (it + 1 < G1_NIT) frag_load((it+1)%G1_SLOTS, 0, Af0, Bf0);
        do_mma(Af1, Bf1);
    }

    // epilogue: row = wm+8g+4h+mt, 16 contiguous cols at n0+wn+16tg (guard vs MTOT)
    int cb = n0 + wn + 16*tg;
    #pragma unroll
    for (int mt = 0; mt < 4; mt++){
        #pragma unroll
        for (int h = 0; h < 2; h++){
            int row = wm + 8*g + 4*h + mt;
            float* Cr = S + (size_t)row*MTOT;
            float4 v0, v1, v2, v3;
            v0.x=acc[mt][0][2*h];   v0.y=acc[mt][1][2*h];   v0.z=acc[mt][2][2*h];   v0.w=acc[mt][3][2*h];
            v1.x=acc[mt][4][2*h];   v1.y=acc[mt][5][2*h];   v1.z=acc[mt][6][2*h];   v1.w=acc[mt][7][2*h];
            v2.x=acc[mt][0][2*h+1]; v2.y=acc[mt][1][2*h+1]; v2.z=acc[mt][2][2*h+1]; v2.w=acc[mt][3][2*h+1];
            v3.x=acc[mt][4][2*h+1]; v3.y=acc[mt][5][2*h+1]; v3.z=acc[mt][6][2*h+1]; v3.w=acc[mt][7][2*h+1];
            if (cb      < MTOT) *(float4*)(Cr + cb     ) = v0;
            if (cb + 4  < MTOT) *(float4*)(Cr + cb + 4 ) = v1;
            if (cb + 8  < MTOT) *(float4*)(Cr + cb + 8 ) = v2;
            if (cb + 12 < MTOT) *(float4*)(Cr + cb + 12) = v3;
        }
    }
}

// =================================================================================
// GEMM2: out[b][m=o][n=t] = sum_c W[b][o][c] * x[b][c][t]  (M=256 full, N tiles 128)
// R15 schedule; 6-slot ring, issue lead 5, wait<3> (stages it and it+1 guaranteed;
// up to 3 stages / 96KB outstanding after the wait). Batched grid (NOT persistent).
// =================================================================================
#define G2_STG 32768            /* A 16KB + B 16KB */
#define G2_SLOTS 6
#define G2_SMEM (G2_SLOTS*G2_STG)   /* 196608 */
#define G2_NIT 9                /* 288/32 */

__global__ void __launch_bounds__(256,1) gemm2_h(
    const __half2* __restrict__ WP, const float* __restrict__ xg, float* __restrict__ out)
{
    extern __shared__ char sm[];
    int b = blockIdx.z;
    const __half2* Ah = WP + (size_t)b*QC*O_;
    const float*   Bx = xg + (size_t)b*C_*T_;
    float*         C  = out + (size_t)b*O_*T_;

    int n0 = blockIdx.x*128;
    int tid = threadIdx.x, warp = tid>>5, lane = tid&31;
    int g = lane>>2, tg = lane&3;
    int wm = (warp>>1)*64, wn = (warp&1)*64;
    const uint32_t xm = XM(tg);

    float acc[4][8][4];
    #pragma unroll
    for (int mt = 0; mt < 4; mt++)
        #pragma unroll
        for (int nt = 0; nt < 8; nt++)
            #pragma unroll
            for (int e = 0; e < 4; e++) acc[mt][nt][e] = 0.f;

    auto load_stage = [&](int s, int it){
        char* dA = sm + s*G2_STG;
        char* dB = dA + 16384;
        int q0 = it*16, k0 = it*32;
        #pragma unroll
        for (int j = 0; j < 4; j++){       // A: 16 rows x 64 chunks
            int id = tid + 256*j;
            int r = id >> 6, ch = id & 63;
            uint32_t xr = XM(r&3);
            const char* src = (const char*)(Ah + (size_t)(q0+r)*O_) + 16*ch;
            cpa16(dA + r*1024 + (((uint32_t)(16*ch)) ^ xr), src);
        }
        #pragma unroll
        for (int j = 0; j < 4; j++){       // B: 32 fp32 rows x 32 chunks
            int id = tid + 256*j;
            int r = id >> 5, ch = id & 31;
            uint32_t xr = XM((r>>1)&3);
            bool pr = (k0 + r) < C_;
            const char* src = (const char*)(Bx + (size_t)(k0+r)*T_ + n0) + 16*ch;
            cpa16p(dB + r*512 + (((uint32_t)(16*ch)) ^ xr), src, pr);
        }
        cp_commit();
    };

    uint32_t Af0[16], Bp0[16], Af1[16], Bp1[16];

    auto frag_load = [&](int slot, int h, uint32_t* Af, uint32_t* Bp){
        const char* dA = sm + slot*G2_STG;
        const char* dB = dA + 16384;
        int rA = tg + 8*h;
        uint32_t ab = (uint32_t)((wm + 8*g)*4);
        uint4 A0 = *(const uint4*)(dA + rA*1024     + ((ab   ) ^ xm));
        uint4 A1 = *(const uint4*)(dA + rA*1024     + ((ab+16) ^ xm));
        uint4 A2 = *(const uint4*)(dA + (rA+4)*1024 + ((ab   ) ^ xm));
        uint4 A3 = *(const uint4*)(dA + (rA+4)*1024 + ((ab+16) ^ xm));
        Af[0]=A0.x;  Af[1]=A0.y;  Af[2]=A0.z;  Af[3]=A0.w;
        Af[4]=A1.x;  Af[5]=A1.y;  Af[6]=A1.z;  Af[7]=A1.w;
        Af[8]=A2.x;  Af[9]=A2.y;  Af[10]=A2.z; Af[11]=A2.w;
        Af[12]=A3.x; Af[13]=A3.y; Af[14]=A3.z; Af[15]=A3.w;

        int rB = 16*h;
        uint32_t bb = (uint32_t)((wn + 8*g)*4);
        uint32_t c0 = (bb   ) ^ xm;
        uint32_t c1 = (bb+16) ^ xm;
        float4 e0 = *(const float4*)(dB + (rB+2*tg  )*512 + c0);
        float4 e1 = *(const float4*)(dB + (rB+2*tg  )*512 + c1);
        float4 o0 = *(const float4*)(dB + (rB+2*tg+1)*512 + c0);
        float4 o1 = *(const float4*)(dB + (rB+2*tg+1)*512 + c1);
        float4 E0 = *(const float4*)(dB + (rB+2*tg+8)*512 + c0);
        float4 E1 = *(const float4*)(dB + (rB+2*tg+8)*512 + c1);
        float4 O0 = *(const float4*)(dB + (rB+2*tg+9)*512 + c0);
        float4 O1 = *(const float4*)(dB + (rB+2*tg+9)*512 + c1);
        Bp[0]=packh(e0.x,o0.x); Bp[1]=packh(e0.y,o0.y); Bp[2]=packh(e0.z,o0.z); Bp[3]=packh(e0.w,o0.w);
        Bp[4]=packh(e1.x,o1.x); Bp[5]=packh(e1.y,o1.y); Bp[6]=packh(e1.z,o1.z); Bp[7]=packh(e1.w,o1.w);
        Bp[8]=packh(E0.x,O0.x); Bp[9]=packh(E0.y,O0.y); Bp[10]=packh(E0.z,O0.z); Bp[11]=packh(E0.w,O0.w);
        Bp[12]=packh(E1.x,O1.x);Bp[13]=packh(E1.y,O1.y);Bp[14]=packh(E1.z,O1.z); Bp[15]=packh(E1.w,O1.w);
    };

    auto do_mma = [&](const uint32_t* Af, const uint32_t* Bp){
        #pragma unroll
        for (int mt = 0; mt < 4; mt++)
            #pragma unroll
            for (int nt = 0; nt < 8; nt++)
                MMA16(acc[mt][nt], Af[mt], Af[4+mt], Af[8+mt], Af[12+mt], Bp[nt], Bp[8+nt]);
    };

    // prologue: 5 stages committed; wait<3> -> stages 0,1 resident
    load_stage(0,0); load_stage(1,1); load_stage(2,2); load_stage(3,3); load_stage(4,4);
    cp_wait<3>();
    __syncthreads();
    frag_load(0, 0, Af0, Bp0);

    #pragma unroll 1
    for (int it = 0; it < G2_NIT; it++){
        if (it > 0){ cp_wait<3>(); __syncthreads(); }   // stages <= it+1 resident
        if (it + 5 < G2_NIT) load_stage((it+5)%G2_SLOTS, it+5);   // slot == (it-1)%6
        else                 cp_commit();
        frag_load(it%G2_SLOTS, 1, Af1, Bp1);
        do_mma(Af0, Bp0);
        if (it + 1 < G2_NIT) frag_load((it+1)%G2_SLOTS, 0, Af0, Bp0);
        do_mma(Af1, Bp1);
    }

    int cb = n0 + wn + 16*tg;   // always in-bounds (T_ multiple of 128)
    #pragma unroll
    for (int mt = 0; mt < 4; mt++){
        #pragma unroll
        for (int h = 0; h < 2; h++){
            int row = wm + 8*g + 4*h + mt;
            float* Cr = C + (size_t)row*T_;
            float4 v0, v1, v2, v3;
            v0.x=acc[mt][0][2*h];   v0.y=acc[mt][1][2*h];   v0.z=acc[mt][2][2*h];   v0.w=acc[mt][3][2*h];
            v1.x=acc[mt][4][2*h];   v1.y=acc[mt][5][2*h];   v1.z=acc[mt][6][2*h];   v1.w=acc[mt][7][2*h];
            v2.x=acc[mt][0][2*h+1]; v2.y=acc[mt][1][2*h+1]; v2.z=acc[mt][2][2*h+1]; v2.w=acc[mt][3][2*h+1];
            v3.x=acc[mt][4][2*h+1]; v3.y=acc[mt][5][2*h+1]; v3.z=acc[mt][6][2*h+1]; v3.w=acc[mt][7][2*h+1];
            *(float4*)(Cr + cb     ) = v0;
            *(float4*)(Cr + cb + 4 ) = v1;
            *(float4*)(Cr + cb + 8 ) = v2;
            *(float4*)(Cr + cb + 12) = v3;
        }
    }
}

// ---------------- softmax over C, writing packed fp16 W^T directly ----------------
#define WPITCH 277
__global__ void __launch_bounds__(256) softmaxT_kernel(
    const float* __restrict__ S, const unsigned char* __restrict__ mask,
    __half2* __restrict__ WP)
{
    __shared__ float wsm[32*WPITCH];
    const float NEG_INF = __int_as_float(0xff800000);
    int o0 = blockIdx.x * 32;
    int b  = blockIdx.y;
    int tid = threadIdx.x, wid = tid >> 5, lane = tid & 31;
    const unsigned char* mrow = mask + (size_t)b * C_;

    #pragma unroll
    for (int p = 0; p < 4; p++){
        int o = 4*wid + p;
        const float* row = S + (size_t)(o0 + o) * MTOT + (size_t)b * C_;
        float v[9];
        float vmax = NEG_INF;
        #pragma unroll
        for (int it = 0; it < 9; it++){
            int c = lane + 32*it;
            float s = NEG_INF;
            if (c < C_) s = mrow[c] ? NEG_INF : row[c];
            v[it] = s;
            vmax = fmaxf(vmax, s);
        }
        #pragma unroll
        for (int off = 16; off; off >>= 1)
            vmax = fmaxf(vmax, __shfl_xor_sync(0xffffffffu, vmax, off));
        float e[9], sum = 0.f;
        #pragma unroll
        for (int it = 0; it < 9; it++){
            e[it] = __expf(v[it] - vmax);
            sum += e[it];
        }
        #pragma unroll
        for (int off = 16; off; off >>= 1)
            sum += __shfl_xor_sync(0xffffffffu, sum, off);
        float inv = 1.f / sum;
        #pragma unroll
        for (int it = 0; it < 9; it++){
            int c = lane + 32*it;
            if (c < C_) wsm[o*WPITCH + c] = e[it] * inv;
        }
    }
    __syncthreads();

    __half2* base = WP + (size_t)b * QC * O_ + o0;
    for (int q = wid; q < QC; q += 8){
        int c0 = 2*q, c1 = 2*q + 1;
        float w0 = (c0 < C_) ? wsm[lane*WPITCH + c0] : 0.f;
        float w1 = (c1 < C_) ? wsm[lane*WPITCH + c1] : 0.f;
        base[(size_t)q * O_ + lane] = __floats2half2_rn(w0, w1);
    }
}

// ---------------- launcher ----------------
extern "C" void kernel_launch(void* const* d_in, const int* in_sizes, int n_in,
                              void* d_out, int out_size)
{
    const float* x = nullptr;
    const float* positions = nullptr;
    const unsigned char* mask = nullptr;
    const float* heads = nullptr;
    for (int i = 0; i < n_in; i++){
        long long s = in_sizes[i];
        if      (s == (long long)B_*C_*T_) x         = (const float*)d_in[i];
        else if (s == (long long)B_*C_*2 ) positions = (const float*)d_in[i];
        else if (s == (long long)B_*C_   ) mask      = (const unsigned char*)d_in[i];
        else if (s == (long long)O_*D_   ) heads     = (const float*)d_in[i];
    }

    __half2 *pEP, *pHP, *pWP;
    float *pS;
    cudaGetSymbolAddress((void**)&pEP, g_EP);
    cudaGetSymbolAddress((void**)&pHP, g_hP);
    cudaGetSymbolAddress((void**)&pS,  g_S);
    cudaGetSymbolAddress((void**)&pWP, g_WP);

    cudaFuncSetAttribute(gemm1_h, cudaFuncAttributeMaxDynamicSharedMemorySize, G1_SMEM);
    cudaFuncSetAttribute(gemm2_h, cudaFuncAttributeMaxDynamicSharedMemorySize, G2_SMEM);

    // 1) heads -> packed fp16 [q][o]
    hprep_kernel<<<dim3(QD/32, O_/32), dim3(32,8)>>>(heads);

    // 2) E -> packed fp16 pairs [q][n] (pad cols zero)
    etgen_kernel<<<NPAD/32, 256>>>(positions);

    // 3) scores: M=256(full), N=17472, K=2048   — 137 CTAs, single wave
    gemm1_h<<<dim3(NPAD/128, 1, 1), 256, G1_SMEM>>>(pHP, pEP, pS);

    // 4) softmax -> packed W^T [b][q][o]
    softmaxT_kernel<<<dim3(O_/32, B_), 256>>>(pS, mask, pWP);

    // 5) out[b] = W[b] @ x[b]: M=256(full), N=2048, K=288 (273 real), batched
    gemm2_h<<<dim3(T_/128, 1, B_), 256, G2_SMEM>>>(pWP, x, (float*)d_out);
}